// round 3
// baseline (speedup 1.0000x reference)
#include <cuda_runtime.h>
#include <math.h>

#define N_NODES 100000
#define N_EDGES 6400000
#define THETA   1.0f
#define EQUIL_STEPS 100
#define REC_STEPS   200
#define TOTAL_STEPS (EQUIL_STEPS + REC_STEPS)

// ---------------- device scratch (sanctioned: __device__ globals) -------------
// Packed CSR edge array: low 32 bits = src index, high 32 bits = f32 weight bits.
__device__ unsigned long long g_edges[N_EDGES];
__device__ int   g_rowptr[N_NODES + 1];
__device__ int   g_cursor[N_NODES];
__device__ int   g_deg[N_NODES];
__device__ float g_s[2][N_NODES];
__device__ int   g_is64;   // 1 if edge_index stored as int64, 0 if int32

// ---------------- dtype detection --------------------------------------------
// If edge_index is int64 little-endian with values in [0, 1e5), the int32 view
// has 0 at every odd position. Probe 128 odd words (first 1KB — safe in both
// layouts since the buffer is >= 2*N_EDGES int32 either way).
__global__ void detect_kernel(const int* __restrict__ ei32) {
    int all_zero = 1;
    for (int k = 0; k < 128; k++)
        if (ei32[2 * k + 1] != 0) { all_zero = 0; break; }
    g_is64 = all_zero;
}

// ---------------- preprocessing kernels --------------------------------------

__global__ void zero_deg_kernel() {
    int i = blockIdx.x * blockDim.x + threadIdx.x;
    if (i < N_NODES) g_deg[i] = 0;
}

__device__ __forceinline__ int load_idx(const int* __restrict__ ei32,
                                        long long pos, int is64) {
    // element `pos` of the logical (2*N_EDGES,) index array
    return is64 ? ei32[2 * pos] : ei32[pos];
}

__global__ void hist_kernel(const int* __restrict__ ei32) {
    long long i = blockIdx.x * blockDim.x + threadIdx.x;   // exact grid
    int is64 = g_is64;
    int d = load_idx(ei32, (long long)N_EDGES + i, is64);
    if ((unsigned)d < N_NODES) atomicAdd(&g_deg[d], 1);
}

// Single-CTA exclusive scan of g_deg -> g_rowptr (+ copy to g_cursor).
__global__ void scan_kernel() {
    __shared__ int ssum[1024];
    const int C = (N_NODES + 1023) / 1024;           // 98
    int t = threadIdx.x;
    int begin = t * C;
    int end   = begin + C; if (end > N_NODES) end = N_NODES;
    if (begin > N_NODES) begin = N_NODES;

    int sum = 0;
    for (int i = begin; i < end; i++) sum += g_deg[i];
    ssum[t] = sum;
    __syncthreads();

    for (int off = 1; off < 1024; off <<= 1) {
        int v = (t >= off) ? ssum[t - off] : 0;
        __syncthreads();
        ssum[t] += v;
        __syncthreads();
    }

    int run = (t == 0) ? 0 : ssum[t - 1];
    for (int i = begin; i < end; i++) {
        g_rowptr[i] = run;
        g_cursor[i] = run;
        run += g_deg[i];
    }
    if (t == 1023) g_rowptr[N_NODES] = ssum[1023];
}

__global__ void scatter_kernel(const int* __restrict__ ei32,
                               const float* __restrict__ W) {
    long long i = blockIdx.x * blockDim.x + threadIdx.x;   // exact grid
    int is64 = g_is64;
    int s = load_idx(ei32, i, is64);
    int d = load_idx(ei32, (long long)N_EDGES + i, is64);
    if ((unsigned)d >= N_NODES || (unsigned)s >= N_NODES) return;
    int p = atomicAdd(&g_cursor[d], 1);
    unsigned long long pk = (unsigned long long)(unsigned int)s
                          | ((unsigned long long)__float_as_uint(W[i]) << 32);
    g_edges[p] = pk;
}

__global__ void init_state_kernel(const float* __restrict__ x) {
    int i = blockIdx.x * blockDim.x + threadIdx.x;
    if (i < N_NODES) g_s[0][i] = x[i];
}

// ---------------- main step: warp-per-node segmented reduction ----------------

__global__ __launch_bounds__(256) void step_kernel(int buf, float* __restrict__ raster_row) {
    const float* __restrict__ s_old = g_s[buf];
    float*       __restrict__ s_new = g_s[buf ^ 1];

    int gwid = (blockIdx.x * blockDim.x + threadIdx.x) >> 5;  // exact: 100000 warps
    int lane = threadIdx.x & 31;

    int beg = g_rowptr[gwid];
    int end = g_rowptr[gwid + 1];

    float acc = 0.0f;
    for (int i = beg + lane; i < end; i += 32) {
        unsigned long long pk = __ldg(&g_edges[i]);
        int   src = (int)(unsigned int)(pk & 0xffffffffull);
        float w   = __uint_as_float((unsigned int)(pk >> 32));
        acc += w * __ldg(&s_old[src]);
    }

    #pragma unroll
    for (int o = 16; o > 0; o >>= 1)
        acc += __shfl_xor_sync(0xffffffffu, acc, o);

    if (lane == 0) {
        float v = 1.0f / (1.0f + __expf(THETA - acc));
        s_new[gwid] = v;
        if (raster_row) raster_row[gwid] = v;
    }
}

// ---------------- launch --------------------------------------------------------

extern "C" void kernel_launch(void* const* d_in, const int* in_sizes, int n_in,
                              void* d_out, int out_size) {
    const float* x    = (const float*)d_in[0];       // (N_NODES, 1) f32
    const float* W    = (const float*)d_in[1];       // (N_EDGES,)   f32
    const int*   ei32 = (const int*)d_in[2];         // (2, N_EDGES) int32 or int64 view
    float* out = (float*)d_out;                       // (REC_STEPS, N_NODES) f32

    // ---- detect index dtype, then build CSR
    detect_kernel<<<1, 1>>>(ei32);
    zero_deg_kernel<<<(N_NODES + 255) / 256, 256>>>();
    hist_kernel<<<N_EDGES / 256, 256>>>(ei32);
    scan_kernel<<<1, 1024>>>();
    scatter_kernel<<<N_EDGES / 256, 256>>>(ei32, W);
    init_state_kernel<<<(N_NODES + 255) / 256, 256>>>(x);

    // ---- 300 steps, warp per node (8 nodes / 256-thread block)
    const int step_blocks = N_NODES / 8;              // 12500, exact
    for (int t = 0; t < TOTAL_STEPS; t++) {
        float* raster_row = (t >= EQUIL_STEPS)
                          ? out + (size_t)(t - EQUIL_STEPS) * N_NODES
                          : nullptr;
        step_kernel<<<step_blocks, 256>>>(t & 1, raster_row);
    }
}

// round 4
// speedup vs baseline: 1.3052x; 1.3052x over previous
#include <cuda_runtime.h>
#include <cuda_fp16.h>
#include <math.h>

#define N_NODES 100000
#define N_EDGES 6400000
#define THETA   1.0f
#define EQUIL_STEPS 100
#define REC_STEPS   200
#define TOTAL_STEPS (EQUIL_STEPS + REC_STEPS)
#define GRID_CTAS   148
#define CTA_THREADS 1024
#define NODES_PER_CTA ((N_NODES + GRID_CTAS - 1) / GRID_CTAS)   // 676
#define SMEM_BYTES  (N_NODES * 2)                               // 200000 B fp16 state

// ---------------- device scratch (sanctioned: __device__ globals) -------------
__device__ unsigned g_src[N_EDGES];        // CSR src indices
__device__ __half   g_wgt[N_EDGES];        // CSR weights (fp16)
__device__ int      g_rowptr[N_NODES + 1];
__device__ int      g_cursor[N_NODES];
__device__ int      g_deg[N_NODES];
__device__ __half   g_state[2][N_NODES];   // double-buffered fp16 state
__device__ int      g_is64;
__device__ unsigned g_bar;                 // grid-barrier counter (reset each launch)

// ---------------- dtype detection --------------------------------------------
// int64-LE edge_index with values < 2^31 has 0 at every odd int32 position.
__global__ void detect_kernel(const int* __restrict__ ei32) {
    int all_zero = 1;
    for (int k = 0; k < 128; k++)
        if (ei32[2 * k + 1] != 0) { all_zero = 0; break; }
    g_is64 = all_zero;
}

// ---------------- preprocessing ------------------------------------------------
__global__ void zero_deg_kernel() {
    int i = blockIdx.x * blockDim.x + threadIdx.x;
    if (i < N_NODES) g_deg[i] = 0;
}

__device__ __forceinline__ int load_idx(const int* __restrict__ ei32,
                                        long long pos, int is64) {
    return is64 ? ei32[2 * pos] : ei32[pos];
}

__global__ void hist_kernel(const int* __restrict__ ei32) {
    long long i = blockIdx.x * blockDim.x + threadIdx.x;   // exact grid
    int is64 = g_is64;
    int d = load_idx(ei32, (long long)N_EDGES + i, is64);
    if ((unsigned)d < N_NODES) atomicAdd(&g_deg[d], 1);
}

// 1-CTA scan, vectorized: 1000 threads x 100 nodes (25 int4 each).
__global__ void scan_kernel() {
    __shared__ int ssum[1024];
    int t = threadIdx.x;
    int sum = 0;
    if (t < 1000) {
        const int4* d4 = (const int4*)g_deg + t * 25;
        #pragma unroll
        for (int i = 0; i < 25; i++) {
            int4 v = d4[i];
            sum += v.x + v.y + v.z + v.w;
        }
    }
    ssum[t] = sum;
    __syncthreads();
    for (int off = 1; off < 1024; off <<= 1) {
        int v = (t >= off) ? ssum[t - off] : 0;
        __syncthreads();
        ssum[t] += v;
        __syncthreads();
    }
    if (t < 1000) {
        int run = (t == 0) ? 0 : ssum[t - 1];
        int base = t * 100;
        #pragma unroll 4
        for (int i = 0; i < 100; i++) {
            g_rowptr[base + i] = run;
            g_cursor[base + i] = run;
            run += g_deg[base + i];
        }
    }
    if (t == 1023) g_rowptr[N_NODES] = ssum[1023];
}

__global__ void scatter_kernel(const int* __restrict__ ei32,
                               const float* __restrict__ W) {
    long long i = blockIdx.x * blockDim.x + threadIdx.x;   // exact grid
    int is64 = g_is64;
    int s = load_idx(ei32, i, is64);
    int d = load_idx(ei32, (long long)N_EDGES + i, is64);
    if ((unsigned)d >= N_NODES || (unsigned)s >= N_NODES) return;
    int p = atomicAdd(&g_cursor[d], 1);
    g_src[p] = (unsigned)s;
    g_wgt[p] = __float2half_rn(W[i]);
}

__global__ void init_state_kernel(const float* __restrict__ x) {
    int i = blockIdx.x * blockDim.x + threadIdx.x;
    if (i < N_NODES) g_state[0][i] = __float2half_rn(x[i]);
    if (i == 0) g_bar = 0u;                 // reset grid barrier every launch
}

// ---------------- persistent simulation kernel --------------------------------
// 148 CTAs (1/SM, co-resident), full fp16 state staged in smem each step,
// warp-per-node segmented reduction, software grid barrier between steps.
__global__ __launch_bounds__(CTA_THREADS, 1)
void sim_kernel(float* __restrict__ out) {
    extern __shared__ __half s_sh[];        // 100000 halves = 200000 B
    const int tid  = threadIdx.x;
    const int wid  = tid >> 5;
    const int lane = tid & 31;
    const int nbeg = blockIdx.x * NODES_PER_CTA;
    const int nend = (nbeg + NODES_PER_CTA < N_NODES) ? nbeg + NODES_PER_CTA : N_NODES;

    for (int t = 0; t < TOTAL_STEPS; t++) {
        // ---- stage full state into smem (L2-only loads: buffer is rewritten
        //      every other step, L1 would serve stale lines)
        const uint4* sv = (const uint4*)g_state[t & 1];
        uint4*       dv = (uint4*)s_sh;
        #pragma unroll 4
        for (int i = tid; i < (N_NODES * 2 / 16); i += CTA_THREADS)   // 12500 uint4
            dv[i] = __ldcg(&sv[i]);
        __syncthreads();

        __half* __restrict__ s_new = g_state[(t + 1) & 1];
        float*  __restrict__ rrow  = (t >= EQUIL_STEPS)
                                   ? out + (size_t)(t - EQUIL_STEPS) * N_NODES
                                   : (float*)0;

        // ---- warp-per-node segmented reduction, gather from smem
        for (int n = nbeg + wid; n < nend; n += 32) {
            int beg = __ldg(&g_rowptr[n]);
            int end = __ldg(&g_rowptr[n + 1]);
            float acc = 0.0f;
            for (int i = beg + lane; i < end; i += 32) {
                unsigned s = __ldg(&g_src[i]);
                float    w = __half2float(__ldg(&g_wgt[i]));
                acc += w * __half2float(s_sh[s]);
            }
            #pragma unroll
            for (int o = 16; o > 0; o >>= 1)
                acc += __shfl_xor_sync(0xffffffffu, acc, o);
            if (lane == 0) {
                float v = 1.0f / (1.0f + __expf(THETA - acc));
                s_new[n] = __float2half_rn(v);
                if (rrow) rrow[n] = v;
            }
        }

        // ---- grid barrier (all 148 CTAs co-resident: 1 CTA/SM by smem)
        __syncthreads();
        if (tid == 0) {
            __threadfence();                         // publish s_new / raster
            atomicAdd(&g_bar, 1u);
            unsigned target = (unsigned)GRID_CTAS * (unsigned)(t + 1);
            while (*(volatile unsigned*)&g_bar < target) { }
            __threadfence();                         // see peers' s_new
        }
        __syncthreads();
    }
}

// ---------------- launch --------------------------------------------------------
extern "C" void kernel_launch(void* const* d_in, const int* in_sizes, int n_in,
                              void* d_out, int out_size) {
    const float* x    = (const float*)d_in[0];   // (N_NODES, 1) f32
    const float* W    = (const float*)d_in[1];   // (N_EDGES,)   f32
    const int*   ei32 = (const int*)d_in[2];     // (2, N_EDGES) int32 view (int64 detected)
    float* out = (float*)d_out;                   // (REC_STEPS, N_NODES) f32

    cudaFuncSetAttribute(sim_kernel,
                         cudaFuncAttributeMaxDynamicSharedMemorySize, SMEM_BYTES);

    // ---- build CSR (per launch; deterministic)
    detect_kernel<<<1, 1>>>(ei32);
    zero_deg_kernel<<<(N_NODES + 255) / 256, 256>>>();
    hist_kernel<<<N_EDGES / 256, 256>>>(ei32);
    scan_kernel<<<1, 1024>>>();
    scatter_kernel<<<N_EDGES / 256, 256>>>(ei32, W);
    init_state_kernel<<<(N_NODES + 255) / 256, 256>>>(x);

    // ---- one persistent kernel runs all 300 steps
    sim_kernel<<<GRID_CTAS, CTA_THREADS, SMEM_BYTES>>>(out);
}

// round 5
// speedup vs baseline: 2.1546x; 1.6507x over previous
#include <cuda_runtime.h>
#include <cuda_fp16.h>
#include <math.h>

#define N_NODES 100000
#define N_EDGES 6400000
#define THETA   1.0f
#define EQUIL_STEPS 100
#define REC_STEPS   200
#define TOTAL_STEPS (EQUIL_STEPS + REC_STEPS)
#define GRID_CTAS   148
#define CTA_THREADS 1024
#define NPC         676            // nodes per CTA (148*676 = 100048 >= 100000)
#define MAXDEG      160            // Poisson(64): P(deg>=160) ~ 1e-23
#define SMEM_BYTES  (N_NODES * 2)  // full fp16 state in shared memory

// ---------------- device scratch (sanctioned: __device__ globals) -------------
// ELL column-major per CTA: slot j of node (nbeg+r) at  cta*(NPC*MAXDEG) + j*NPC + r
__device__ unsigned g_esrc[(size_t)GRID_CTAS * NPC * MAXDEG];   // 64 MB
__device__ __half   g_ewgt[(size_t)GRID_CTAS * NPC * MAXDEG];   // 32 MB
__device__ int      g_deg[N_NODES];
__device__ int      g_cursor[N_NODES];
__device__ __half   g_state[2][N_NODES];
__device__ int      g_is64;
__device__ unsigned g_bar;

// ---------------- dtype detection --------------------------------------------
__global__ void detect_kernel(const int* __restrict__ ei32) {
    int all_zero = 1;
    for (int k = 0; k < 128; k++)
        if (ei32[2 * k + 1] != 0) { all_zero = 0; break; }
    g_is64 = all_zero;
}

// ---------------- preprocessing ------------------------------------------------
__global__ void zero_kernel() {
    int i = blockIdx.x * blockDim.x + threadIdx.x;
    if (i < N_NODES) { g_deg[i] = 0; g_cursor[i] = 0; }
    if (i == 0) g_bar = 0u;
}

__device__ __forceinline__ int load_idx(const int* __restrict__ ei32,
                                        long long pos, int is64) {
    return is64 ? ei32[2 * pos] : ei32[pos];
}

__global__ void hist_kernel(const int* __restrict__ ei32) {
    long long i = blockIdx.x * blockDim.x + threadIdx.x;   // exact grid
    int is64 = g_is64;
    int d = load_idx(ei32, (long long)N_EDGES + i, is64);
    if ((unsigned)d < N_NODES) atomicAdd(&g_deg[d], 1);
}

__global__ void scatter_kernel(const int* __restrict__ ei32,
                               const float* __restrict__ W) {
    long long i = blockIdx.x * blockDim.x + threadIdx.x;   // exact grid
    int is64 = g_is64;
    int s = load_idx(ei32, i, is64);
    int d = load_idx(ei32, (long long)N_EDGES + i, is64);
    if ((unsigned)d >= N_NODES || (unsigned)s >= N_NODES) return;
    int c = d / NPC;
    int r = d - c * NPC;
    int j = atomicAdd(&g_cursor[d], 1);
    if (j < MAXDEG) {
        size_t idx = (size_t)c * (NPC * MAXDEG) + (size_t)j * NPC + r;
        g_esrc[idx] = (unsigned)s;
        g_ewgt[idx] = __float2half_rn(W[i]);
    }
}

__global__ void init_state_kernel(const float* __restrict__ x) {
    int i = blockIdx.x * blockDim.x + threadIdx.x;
    if (i < N_NODES) g_state[0][i] = __float2half_rn(x[i]);
}

// ---------------- persistent simulation kernel --------------------------------
// 148 CTAs (1/SM via 200KB smem), full fp16 state staged in smem each step.
// Thread-per-node ELL gather: coalesced edge loads, no inter-thread reduction.
__global__ __launch_bounds__(CTA_THREADS, 1)
void sim_kernel(float* __restrict__ out) {
    extern __shared__ __half s_sh[];             // 100000 halves
    const int tid  = threadIdx.x;
    const int n    = blockIdx.x * NPC + tid;
    const bool active = (tid < NPC) && (n < N_NODES);

    int deg = 0;
    if (active) {
        deg = g_deg[n];
        if (deg > MAXDEG) deg = MAXDEG;
    }
    const unsigned* __restrict__ esrc0 =
        g_esrc + (size_t)blockIdx.x * (NPC * MAXDEG) + tid;
    const __half* __restrict__ ewgt0 =
        g_ewgt + (size_t)blockIdx.x * (NPC * MAXDEG) + tid;

    for (int t = 0; t < TOTAL_STEPS; t++) {
        // ---- stage full state into smem (bypass L1: buffer rewritten each step)
        const uint4* sv = (const uint4*)g_state[t & 1];
        uint4*       dv = (uint4*)s_sh;
        #pragma unroll 4
        for (int i = tid; i < (N_NODES * 2 / 16); i += CTA_THREADS)  // 12500
            dv[i] = __ldcg(&sv[i]);
        __syncthreads();

        if (active) {
            const unsigned* ps = esrc0;
            const __half*   pw = ewgt0;
            float a0 = 0.0f, a1 = 0.0f;
            int j = 0;
            for (; j + 2 <= deg; j += 2) {
                unsigned s0 = __ldg(ps);
                unsigned s1 = __ldg(ps + NPC);
                float    w0 = __half2float(__ldg(pw));
                float    w1 = __half2float(__ldg(pw + NPC));
                a0 += w0 * __half2float(s_sh[s0]);
                a1 += w1 * __half2float(s_sh[s1]);
                ps += 2 * NPC;
                pw += 2 * NPC;
            }
            if (j < deg)
                a0 += __half2float(__ldg(pw)) * __half2float(s_sh[__ldg(ps)]);

            float v = 1.0f / (1.0f + __expf(THETA - (a0 + a1)));
            g_state[(t + 1) & 1][n] = __float2half_rn(v);
            if (t >= EQUIL_STEPS)
                out[(size_t)(t - EQUIL_STEPS) * N_NODES + n] = v;
        }

        // ---- software grid barrier (all 148 CTAs co-resident: 1 CTA/SM)
        __syncthreads();
        if (tid == 0) {
            __threadfence();                     // publish s_new
            atomicAdd(&g_bar, 1u);
            unsigned target = (unsigned)GRID_CTAS * (unsigned)(t + 1);
            while (*(volatile unsigned*)&g_bar < target) { }
            __threadfence();                     // see peers' s_new
        }
        __syncthreads();
    }
}

// ---------------- launch --------------------------------------------------------
extern "C" void kernel_launch(void* const* d_in, const int* in_sizes, int n_in,
                              void* d_out, int out_size) {
    const float* x    = (const float*)d_in[0];   // (N_NODES, 1) f32
    const float* W    = (const float*)d_in[1];   // (N_EDGES,)   f32
    const int*   ei32 = (const int*)d_in[2];     // (2, N_EDGES) int32 view
    float* out = (float*)d_out;                   // (REC_STEPS, N_NODES) f32

    cudaFuncSetAttribute(sim_kernel,
                         cudaFuncAttributeMaxDynamicSharedMemorySize, SMEM_BYTES);

    // ---- build ELL (per launch; deterministic work)
    detect_kernel<<<1, 1>>>(ei32);
    zero_kernel<<<(N_NODES + 255) / 256, 256>>>();
    hist_kernel<<<N_EDGES / 256, 256>>>(ei32);
    scatter_kernel<<<N_EDGES / 256, 256>>>(ei32, W);
    init_state_kernel<<<(N_NODES + 255) / 256, 256>>>(x);

    // ---- one persistent kernel runs all 300 steps
    sim_kernel<<<GRID_CTAS, CTA_THREADS, SMEM_BYTES>>>(out);
}

// round 7
// speedup vs baseline: 3.1229x; 1.4494x over previous
#include <cuda_runtime.h>
#include <cuda_fp16.h>
#include <math.h>

#define N_NODES 100000
#define N_EDGES 6400000
#define THETA   1.0f
#define EQUIL_STEPS 100
#define REC_STEPS   200
#define TOTAL_STEPS (EQUIL_STEPS + REC_STEPS)
#define GRID_CTAS   148
#define CTA_THREADS 1024
#define NPC         676            // nodes per CTA (148*676 = 100048 >= 100000)
#define MAXDEG      160            // Poisson(64): P(deg>=160) ~ 1e-23
#define SMEM_BYTES  (N_NODES * 2)  // full fp16 state in shared memory
#define ELL_WORDS_PER_CTA (NPC * MAXDEG)            // 108160
#define ELL_TOTAL  ((size_t)GRID_CTAS * ELL_WORDS_PER_CTA)  // ~16M words = 64MB

// ---------------- device scratch (sanctioned: __device__ globals) -------------
// Packed edge word: bits[0:17) = src, bits[16:32) = fp16 weight with bit0 = 0.
// (bit16 shared: weight LSB is truncated to 0, src bit16 stored there.)
// Group-of-4 ELL: edge j of slot r in CTA c lives at
//   c*ELL_WORDS_PER_CTA + (j>>2)*(NPC*4) + r*4 + (j&3)
// so one uint4 load fetches 4 consecutive edges of one node, coalesced across r.
__device__ unsigned g_ell[ELL_TOTAL];
__device__ int      g_deg[N_NODES];
__device__ int      g_cursor[N_NODES];
__device__ int      g_slot[N_NODES];                 // node -> slot within its CTA
__device__ int      g_pnode[GRID_CTAS * NPC];        // CTA slot -> node
__device__ __half   g_state[2][N_NODES];
__device__ int      g_is64;
__device__ unsigned g_bar;

// ---------------- dtype detection --------------------------------------------
__global__ void detect_kernel(const int* __restrict__ ei32) {
    int all_zero = 1;
    for (int k = 0; k < 128; k++)
        if (ei32[2 * k + 1] != 0) { all_zero = 0; break; }
    g_is64 = all_zero;
}

// ---------------- preprocessing ------------------------------------------------
__global__ void zero_kernel() {
    int i = blockIdx.x * blockDim.x + threadIdx.x;
    if (i < N_NODES) { g_deg[i] = 0; g_cursor[i] = 0; }
    if (i == 0) g_bar = 0u;
}

__global__ void ell_zero_kernel() {                  // zero-padding => w=0 edges
    size_t i = (size_t)blockIdx.x * blockDim.x + threadIdx.x;
    uint4* p = (uint4*)g_ell;
    if (i < ELL_TOTAL / 4) p[i] = make_uint4(0u, 0u, 0u, 0u);
}

__device__ __forceinline__ int load_idx(const int* __restrict__ ei32,
                                        long long pos, int is64) {
    return is64 ? ei32[2 * pos] : ei32[pos];
}

__global__ void hist_kernel(const int* __restrict__ ei32) {
    long long i = blockIdx.x * blockDim.x + threadIdx.x;   // exact grid
    int is64 = g_is64;
    int d = load_idx(ei32, (long long)N_EDGES + i, is64);
    if ((unsigned)d < N_NODES) atomicAdd(&g_deg[d], 1);
}

// Per-CTA counting sort of nodes by (clamped) degree -> uniform warps in sim.
__global__ __launch_bounds__(1024) void sort_kernel() {
    __shared__ int off[MAXDEG + 1];
    int c = blockIdx.x, t = threadIdx.x;
    int nbeg = c * NPC;
    int count = N_NODES - nbeg; if (count > NPC) count = NPC;

    for (int i = t; i <= MAXDEG; i += 1024) off[i] = 0;
    __syncthreads();

    int n = nbeg + t, d = 0;
    if (t < count) {
        d = g_deg[n]; if (d > MAXDEG) d = MAXDEG;
        atomicAdd(&off[d], 1);
    }
    __syncthreads();
    if (t == 0) {                                    // serial prefix over 161 bins
        int run = 0;
        for (int i = 0; i <= MAXDEG; i++) { int h = off[i]; off[i] = run; run += h; }
    }
    __syncthreads();
    if (t < count) {
        int slot = atomicAdd(&off[d], 1);
        g_slot[n] = slot;
        g_pnode[nbeg + slot] = n;
    }
}

__global__ void scatter_kernel(const int* __restrict__ ei32,
                               const float* __restrict__ W) {
    long long i = blockIdx.x * blockDim.x + threadIdx.x;   // exact grid
    int is64 = g_is64;
    int s = load_idx(ei32, i, is64);
    int d = load_idx(ei32, (long long)N_EDGES + i, is64);
    if ((unsigned)d >= N_NODES || (unsigned)s >= N_NODES) return;
    int c = d / NPC;
    int r = g_slot[d];
    int j = atomicAdd(&g_cursor[d], 1);
    if (j < MAXDEG) {
        // fp16 weight, round mantissa LSB away (bit0 -> 0)
        unsigned h = (unsigned)__half_as_ushort(__float2half_rn(W[i]));
        h = (h + (h & 1u)) & 0xFFFEu;
        unsigned pk = (unsigned)s | (h << 16);
        size_t idx = (size_t)c * ELL_WORDS_PER_CTA
                   + (size_t)(j >> 2) * (NPC * 4) + (size_t)r * 4 + (j & 3);
        g_ell[idx] = pk;
    }
}

__global__ void init_state_kernel(const float* __restrict__ x) {
    int i = blockIdx.x * blockDim.x + threadIdx.x;
    if (i < N_NODES) g_state[0][i] = __float2half_rn(x[i]);
}

// ---------------- persistent simulation kernel --------------------------------
__device__ __forceinline__ float dec_edge(unsigned v, const __half* __restrict__ sh) {
    unsigned s = v & 0x1FFFFu;
    __half  w = __ushort_as_half((unsigned short)((v >> 16) & 0xFFFEu));
    return __half2float(w) * __half2float(sh[s]);
}

__global__ __launch_bounds__(CTA_THREADS, 1)
void sim_kernel(float* __restrict__ out) {
    extern __shared__ __half s_sh[];                 // 100000 halves = 200KB
    const int tid  = threadIdx.x;
    const int base = blockIdx.x * NPC;
    int count = N_NODES - base; if (count > NPC) count = NPC;
    const bool active = tid < count;

    int n = 0, deg = 0;
    if (active) {
        n   = g_pnode[base + tid];
        deg = g_deg[n]; if (deg > MAXDEG) deg = MAXDEG;
    }
    const int groups = (deg + 3) >> 2;               // zero-padded tail
    const uint4* __restrict__ e0 =
        (const uint4*)(g_ell + (size_t)blockIdx.x * ELL_WORDS_PER_CTA) + tid;

    for (int t = 0; t < TOTAL_STEPS; t++) {
        // ---- stage full fp16 state into smem (bypass L1: rewritten each step)
        const uint4* sv = (const uint4*)g_state[t & 1];
        uint4*       dv = (uint4*)s_sh;
        #pragma unroll 4
        for (int i = tid; i < (N_NODES * 2 / 16); i += CTA_THREADS)  // 12500
            dv[i] = __ldcg(&sv[i]);
        __syncthreads();

        if (active) {
            const uint4* pe = e0;
            float a0 = 0.0f, a1 = 0.0f;
            for (int g = 0; g < groups; g++) {
                uint4 v = __ldg(pe); pe += NPC;      // 4 edges, one LDG.128
                a0 += dec_edge(v.x, s_sh);
                a1 += dec_edge(v.y, s_sh);
                a0 += dec_edge(v.z, s_sh);
                a1 += dec_edge(v.w, s_sh);
            }
            float val = 1.0f / (1.0f + __expf(THETA - (a0 + a1)));
            g_state[(t + 1) & 1][n] = __float2half_rn(val);
            if (t >= EQUIL_STEPS)
                out[(size_t)(t - EQUIL_STEPS) * N_NODES + n] = val;
        }

        // ---- software grid barrier (148 CTAs co-resident, 1/SM via 200KB smem)
        __syncthreads();
        if (tid == 0) {
            __threadfence();                         // publish s_new / raster
            atomicAdd(&g_bar, 1u);
            unsigned target = (unsigned)GRID_CTAS * (unsigned)(t + 1);
            while (*(volatile unsigned*)&g_bar < target) { }
            __threadfence();                         // observe peers' s_new
        }
        __syncthreads();
    }
}

// ---------------- launch --------------------------------------------------------
extern "C" void kernel_launch(void* const* d_in, const int* in_sizes, int n_in,
                              void* d_out, int out_size) {
    const float* x    = (const float*)d_in[0];   // (N_NODES, 1) f32
    const float* W    = (const float*)d_in[1];   // (N_EDGES,)   f32
    const int*   ei32 = (const int*)d_in[2];     // (2, N_EDGES) int32 view (int64 detected)
    float* out = (float*)d_out;                   // (REC_STEPS, N_NODES) f32

    cudaFuncSetAttribute(sim_kernel,
                         cudaFuncAttributeMaxDynamicSharedMemorySize, SMEM_BYTES);

    // ---- build packed ELL (per launch; deterministic work)
    detect_kernel<<<1, 1>>>(ei32);
    zero_kernel<<<(N_NODES + 255) / 256, 256>>>();
    ell_zero_kernel<<<(int)((ELL_TOTAL / 4 + 255) / 256), 256>>>();
    hist_kernel<<<N_EDGES / 256, 256>>>(ei32);
    sort_kernel<<<GRID_CTAS, 1024>>>();
    scatter_kernel<<<N_EDGES / 256, 256>>>(ei32, W);
    init_state_kernel<<<(N_NODES + 255) / 256, 256>>>(x);

    // ---- one persistent kernel runs all 300 steps
    sim_kernel<<<GRID_CTAS, CTA_THREADS, SMEM_BYTES>>>(out);
}